// round 8
// baseline (speedup 1.0000x reference)
#include <cuda_runtime.h>
#include <cuda_bf16.h>
#include <math.h>

// PCL loss, single kernel, pc table staged in SHARED MEMORY:
//   valid = target != -1
//   p     = (target==0) ? input[i*C + 0] : pc_input[cluster[i]]
//   loss  = sum(valid * (-weight * log(max(p, 1e-12)))) / max(sum(valid), 1)
//
// Perf model: the random pc gather through L1tex costs ~30 sector-wavefronts
// per warp-LDG (the real bottleneck at 14us). Random LDS costs only the bank
// conflict degree (~3.5 cyc). So stage the 16KB table in smem once per CTA.
// Background lanes (t==0) LDG input[idx*21]; inactive lanes read input[0]
// (broadcast sector) to stay branchless with full MLP.

#define C_CLASSES 21
#define EPS 1e-12f
#define NUM_CLUSTERS 4096
#define MAX_BLOCKS 2048
#define THREADS 256
#define EPT 16               // 2 pipelined groups of 8
#define GROUP 8

__device__ float        g_part_sum[MAX_BLOCKS];
__device__ unsigned int g_part_cnt[MAX_BLOCKS];
__device__ unsigned int g_done = 0;   // wraps to 0 via atom.inc bound

__global__ void __launch_bounds__(THREADS, 4)
pcl_fused(const float* __restrict__ input,
          const float* __restrict__ weight,
          const float* __restrict__ pc,
          const int* __restrict__ target,
          const int* __restrict__ cluster,
          int n, float* __restrict__ out) {
    __shared__ float pc_s[NUM_CLUSTERS];

    // Stage the 16KB pc table: 1024 float4 across 256 threads (L2-resident
    // after the first CTA touches it).
    {
        const float4* src = reinterpret_cast<const float4*>(pc);
        #pragma unroll
        for (int k = 0; k < NUM_CLUSTERS / 4 / THREADS; k++) {
            int idx = k * THREADS + threadIdx.x;
            float4 v = __ldg(src + idx);
            *reinterpret_cast<float4*>(pc_s + idx * 4) = v;
        }
    }
    __syncthreads();

    float lsum = 0.0f;
    unsigned int lcnt = 0u;

    const int base = (blockIdx.x * THREADS + threadIdx.x) * EPT;

    if (base + EPT <= n) {
        #pragma unroll
        for (int g = 0; g < EPT / GROUP; g++) {
            const int i = base + g * GROUP;
            // Phase A: 6 independent coalesced 128-bit loads
            int4   t4a = *reinterpret_cast<const int4*>(target + i);
            int4   t4b = *reinterpret_cast<const int4*>(target + i + 4);
            int4   c4a = *reinterpret_cast<const int4*>(cluster + i);
            int4   c4b = *reinterpret_cast<const int4*>(cluster + i + 4);
            float4 w4a = *reinterpret_cast<const float4*>(weight + i);
            float4 w4b = *reinterpret_cast<const float4*>(weight + i + 4);

            int   t[GROUP] = {t4a.x, t4a.y, t4a.z, t4a.w, t4b.x, t4b.y, t4b.z, t4b.w};
            int   c[GROUP] = {c4a.x, c4a.y, c4a.z, c4a.w, c4b.x, c4b.y, c4b.z, c4b.w};
            float w[GROUP] = {w4a.x, w4a.y, w4a.z, w4a.w, w4b.x, w4b.y, w4b.z, w4b.w};

            // Phase B1: background gather via LDG; inactive lanes hit input[0]
            // (single broadcast sector per warp) -> branchless, MLP=8
            float pbg[GROUP];
            #pragma unroll
            for (int k = 0; k < GROUP; k++) {
                const float* a = (t[k] == 0)
                               ? input + (long long)(i + k) * C_CLASSES
                               : input;
                pbg[k] = __ldg(a);
            }
            // Phase B2: foreground gather via shared memory (bank-conflict cost only)
            float pfg[GROUP];
            #pragma unroll
            for (int k = 0; k < GROUP; k++) {
                pfg[k] = pc_s[c[k] & (NUM_CLUSTERS - 1)];
            }

            // Phase C: select + math + masked accumulate
            #pragma unroll
            for (int k = 0; k < GROUP; k++) {
                float p = (t[k] == 0) ? pbg[k] : pfg[k];
                bool valid = (t[k] != -1);
                float l = __logf(fmaxf(p, EPS));
                lsum += valid ? w[k] * l : 0.0f;
                lcnt += valid ? 1u : 0u;
            }
        }
    } else {
        for (int k = base; k < n; k++) {
            int tk = target[k];
            if (tk != -1) {
                float pk = (tk == 0) ? __ldg(input + (long long)k * C_CLASSES)
                                     : pc_s[cluster[k] & (NUM_CLUSTERS - 1)];
                lsum += weight[k] * __logf(fmaxf(pk, EPS));
                lcnt++;
            }
        }
    }

    // warp reduction
    #pragma unroll
    for (int off = 16; off > 0; off >>= 1) {
        lsum += __shfl_xor_sync(0xFFFFFFFFu, lsum, off);
        lcnt += __shfl_xor_sync(0xFFFFFFFFu, lcnt, off);
    }

    // block reduction (8 warps)
    __shared__ float        s_sum[8];
    __shared__ unsigned int s_cnt[8];
    __shared__ int          s_is_last;
    int wid = threadIdx.x >> 5;
    int lid = threadIdx.x & 31;
    if (lid == 0) { s_sum[wid] = lsum; s_cnt[wid] = lcnt; }
    __syncthreads();
    if (threadIdx.x == 0) {
        float        bs = 0.0f;
        unsigned int bc = 0u;
        #pragma unroll
        for (int w8 = 0; w8 < 8; w8++) { bs += s_sum[w8]; bc += s_cnt[w8]; }
        g_part_sum[blockIdx.x] = bs;   // plain STG, ordered by release atom
        g_part_cnt[blockIdx.x] = bc;
        // acq_rel inc: release publishes partials, acquire orders last block's
        // reads; bound gridDim.x-1 self-resets counter (graph-replay safe).
        // No GPU-scope fence => no CCTL.IVALL L1 flush.
        unsigned int prev;
        asm volatile("atom.acq_rel.gpu.global.inc.u32 %0, [%1], %2;"
                     : "=r"(prev)
                     : "l"(&g_done), "r"(gridDim.x - 1)
                     : "memory");
        s_is_last = (prev == gridDim.x - 1) ? 1 : 0;
    }
    __syncthreads();

    if (s_is_last) {
        float        fs = 0.0f;
        unsigned int fc = 0u;
        for (int b = threadIdx.x; b < (int)gridDim.x; b += THREADS) {
            fs += g_part_sum[b];
            fc += g_part_cnt[b];
        }
        #pragma unroll
        for (int off = 16; off > 0; off >>= 1) {
            fs += __shfl_xor_sync(0xFFFFFFFFu, fs, off);
            fc += __shfl_xor_sync(0xFFFFFFFFu, fc, off);
        }
        if (lid == 0) { s_sum[wid] = fs; s_cnt[wid] = fc; }
        __syncthreads();
        if (threadIdx.x == 0) {
            float        ts = 0.0f;
            unsigned int tc = 0u;
            #pragma unroll
            for (int w8 = 0; w8 < 8; w8++) { ts += s_sum[w8]; tc += s_cnt[w8]; }
            float nv = fmaxf((float)tc, 1.0f);
            *out = -ts / nv;
        }
    }
}

extern "C" void kernel_launch(void* const* d_in, const int* in_sizes, int n_in,
                              void* d_out, int out_size) {
    const float* input   = (const float*)d_in[0];   // [N, 21]
    const float* weight  = (const float*)d_in[1];   // [N]
    const float* pc      = (const float*)d_in[2];   // [4096]
    const int*   target  = (const int*)d_in[3];     // [N] int32
    const int*   cluster = (const int*)d_in[4];     // [N] int32
    float* out = (float*)d_out;

    int n = in_sizes[1];   // weight element count == N

    int per_block = THREADS * EPT;                 // 4096
    int blocks = (n + per_block - 1) / per_block;  // 512 for N=2M (single wave)
    if (blocks > MAX_BLOCKS) blocks = MAX_BLOCKS;
    if (blocks < 1) blocks = 1;
    pcl_fused<<<blocks, THREADS>>>(input, weight, pc, target, cluster, n, out);
}